// round 12
// baseline (speedup 1.0000x reference)
#include <cstdint>
#include <cuda_runtime.h>
#include <mma.h>

using namespace nvcuda;

// Problem constants (fixed shapes per reference setup_inputs)
#define NB   8
#define LQ   1024
#define CD   256
#define NH   8
#define NPT  4
#define HD   32
#define HH   128
#define WWp  128
#define HWSZ (HH * WWp)

// ---------------- scratch (device globals; no allocations allowed) ----------
__device__ float4 g_samp[(size_t)NB * LQ * NH * NPT];     // (x_pix, y_pix, attn_w, _)
__device__ float  g_S[(size_t)NB * LQ * CD];              // sampled values [bq][h*32+d]

// ---------------- cp.async helpers ------------------------------------------
__device__ __forceinline__ void cpasync16(void* smem_dst, const void* gmem_src) {
    unsigned int s = (unsigned int)__cvta_generic_to_shared(smem_dst);
    asm volatile("cp.async.cg.shared.global [%0], [%1], 16;" :: "r"(s), "l"(gmem_src));
}
__device__ __forceinline__ void cpasync_commit() {
    asm volatile("cp.async.commit_group;");
}
__device__ __forceinline__ void cpasync_wait0() {
    asm volatile("cp.async.wait_group 0;");
}

// =====================================================================
// kernel 1: offsets + attn weights + sample coords, 32 queries per block
// =====================================================================
#define QB 32
__global__ void __launch_bounds__(256) k_offsets(
    const float* __restrict__ query,
    const float* __restrict__ refp,
    const float* __restrict__ Woff, const float* __restrict__ boff,
    const float* __restrict__ Wattn, const float* __restrict__ battn)
{
    __shared__ float sq[QB][CD + 4];
    __shared__ float sp[QB][96 + 2];

    int q0  = blockIdx.x * QB;
    int tid = threadIdx.x;

    #pragma unroll
    for (int i = 0; i < 8; i++) {
        int id = i * 256 + tid;
        int q = id >> 6, c4 = id & 63;
        float4 v = *(const float4*)(query + (size_t)(q0 + q) * CD + c4 * 4);
        *(float4*)&sq[q][c4 * 4] = v;
    }
    __syncthreads();

    {
        int j0 = tid & 31;
        int qg = tid >> 5;
        float a0[4], a1[4], a2[4];
        #pragma unroll
        for (int m = 0; m < 4; m++) {
            a0[m] = boff[j0];
            a1[m] = boff[j0 + 32];
            a2[m] = battn[j0];
        }
        #pragma unroll 8
        for (int k = 0; k < CD; k++) {
            float w0 = Woff[k * 64 + j0];
            float w1 = Woff[k * 64 + 32 + j0];
            float w2 = Wattn[k * 32 + j0];
            #pragma unroll
            for (int m = 0; m < 4; m++) {
                float s = sq[qg + 8 * m][k];
                a0[m] += w0 * s;
                a1[m] += w1 * s;
                a2[m] += w2 * s;
            }
        }
        #pragma unroll
        for (int m = 0; m < 4; m++) {
            sp[qg + 8 * m][j0]      = a0[m];
            sp[qg + 8 * m][32 + j0] = a1[m];
            sp[qg + 8 * m][64 + j0] = a2[m];
        }
    }
    __syncthreads();

    #pragma unroll
    for (int i = 0; i < 4; i++) {
        int item = i * 256 + tid;
        int q = item >> 5, t32 = item & 31;
        int h = t32 >> 2, p = t32 & 3;

        float l0 = sp[q][64 + h * 4 + 0], l1 = sp[q][64 + h * 4 + 1];
        float l2 = sp[q][64 + h * 4 + 2], l3 = sp[q][64 + h * 4 + 3];
        float m  = fmaxf(fmaxf(l0, l1), fmaxf(l2, l3));
        float e0 = __expf(l0 - m), e1 = __expf(l1 - m);
        float e2 = __expf(l2 - m), e3 = __expf(l3 - m);
        float inv = 1.0f / (e0 + e1 + e2 + e3);
        float ep  = (p == 0) ? e0 : (p == 1) ? e1 : (p == 2) ? e2 : e3;
        float w   = ep * inv;

        int bq = q0 + q;
        float refx = refp[bq * 2 + 0];
        float refy = refp[bq * 2 + 1];
        float ox = sp[q][(h * NPT + p) * 2 + 0];
        float oy = sp[q][(h * NPT + p) * 2 + 1];
        // grid_sample align_corners=False: pix = (ref + off/Dim)*Dim - 0.5
        float x = refx * (float)WWp + ox - 0.5f;
        float y = refy * (float)HH  + oy - 0.5f;
        g_samp[(size_t)bq * (NH * NPT) + t32] = make_float4(x, y, w, 0.f);
    }
}

// =====================================================================
// kernel 2 (FUSED): gather raw memory rows into smem + per-head value
// projection. Block = (64 queries, 1 head). 256 threads.
//   phase 0: cp.async Wv[:, h*32:h*32+32] -> smem B  (lands during gather)
//   phase 1: gather U[64][256] into smem (exact fp32), sw[64] weights
//   phase 2: wmma TF32 GEMM S_tile[64,32] = U @ B; epilogue adds sw*bv
// =====================================================================
#define FBM  64
#define ULD  260                       // U row stride (floats); 260*4=1040B, 16B mult
#define BLD  36                        // B row stride (floats); 36*4=144B, 16B mult
#define U_BYTES (FBM * ULD * 4)        // 66560
#define B_BYTES (CD * BLD * 4)         // 36864
#define SW_OFF  (U_BYTES + B_BYTES)    // 103424
#define SMEM_F  (SW_OFF + FBM * 4)     // 103680

__global__ void __launch_bounds__(256)
k_gathS(const float* __restrict__ memory, const float* __restrict__ Wv,
        const float* __restrict__ bv)
{
    extern __shared__ __align__(16) char dsm[];
    float* Us = (float*)dsm;                       // [64][260]
    float* Bs = (float*)(dsm + U_BYTES);           // [256][36]
    float* sw = (float*)(dsm + SW_OFF);            // [64]

    int tid  = threadIdx.x;
    int wid  = tid >> 5;
    int lane = tid & 31;
    int m0   = blockIdx.x * FBM;                   // query block
    int h    = blockIdx.y;                         // head
    int b    = m0 >> 10;                           // batch (64 | 1024)

    // ---- phase 0: prefetch Wv column slice [256 x 32] ----
    #pragma unroll
    for (int i = 0; i < 8; i++) {
        int f = i * 256 + tid;                     // 2048 float4
        int k = f >> 3, n4 = f & 7;
        cpasync16(&Bs[k * BLD + n4 * 4], Wv + (size_t)k * CD + h * 32 + n4 * 4);
    }
    cpasync_commit();

    // ---- phase 1: gather 8 query rows per warp ----
    const float* mb = memory + (size_t)b * HWSZ * CD + lane * 8;
    for (int i = 0; i < 8; i++) {
        int q  = wid * 8 + i;                      // local query
        int bq = m0 + q;

        float acc[8] = {0.f, 0.f, 0.f, 0.f, 0.f, 0.f, 0.f, 0.f};
        float s = 0.f;

        #pragma unroll
        for (int p = 0; p < NPT; p++) {
            float4 sm = g_samp[(size_t)bq * (NH * NPT) + h * NPT + p];
            float x = sm.x, y = sm.y, w = sm.z;
            float xf = floorf(x), yf = floorf(y);
            int ix = (int)xf, iy = (int)yf;
            float fx = x - xf, fy = y - yf;
            float w00 = w * (1.0f - fy) * (1.0f - fx);
            float w01 = w * (1.0f - fy) * fx;
            float w10 = w * fy * (1.0f - fx);
            float w11 = w * fy * fx;

            if ((unsigned)ix < (WWp - 1) && (unsigned)iy < (HH - 1)) {
                const float* c00 = mb + (size_t)(iy * WWp + ix) * CD;
                float4 a0 = *(const float4*)(c00);
                float4 a1 = *(const float4*)(c00 + 4);
                float4 b0 = *(const float4*)(c00 + CD);
                float4 b1 = *(const float4*)(c00 + CD + 4);
                float4 c0 = *(const float4*)(c00 + WWp * CD);
                float4 c1 = *(const float4*)(c00 + WWp * CD + 4);
                float4 d0 = *(const float4*)(c00 + WWp * CD + CD);
                float4 d1 = *(const float4*)(c00 + WWp * CD + CD + 4);
                acc[0] += w00 * a0.x + w01 * b0.x + w10 * c0.x + w11 * d0.x;
                acc[1] += w00 * a0.y + w01 * b0.y + w10 * c0.y + w11 * d0.y;
                acc[2] += w00 * a0.z + w01 * b0.z + w10 * c0.z + w11 * d0.z;
                acc[3] += w00 * a0.w + w01 * b0.w + w10 * c0.w + w11 * d0.w;
                acc[4] += w00 * a1.x + w01 * b1.x + w10 * c1.x + w11 * d1.x;
                acc[5] += w00 * a1.y + w01 * b1.y + w10 * c1.y + w11 * d1.y;
                acc[6] += w00 * a1.z + w01 * b1.z + w10 * c1.z + w11 * d1.z;
                acc[7] += w00 * a1.w + w01 * b1.w + w10 * c1.w + w11 * d1.w;
                s += w;
            } else {
                #pragma unroll
                for (int cy = 0; cy < 2; cy++) {
                    int yy = iy + cy;
                    if ((unsigned)yy >= HH) continue;
                    #pragma unroll
                    for (int cx = 0; cx < 2; cx++) {
                        int xx = ix + cx;
                        if ((unsigned)xx >= WWp) continue;
                        float cw = cy ? (cx ? w11 : w10) : (cx ? w01 : w00);
                        const float* cp = mb + (size_t)(yy * WWp + xx) * CD;
                        float4 u0 = *(const float4*)(cp);
                        float4 u1 = *(const float4*)(cp + 4);
                        acc[0] += cw * u0.x; acc[1] += cw * u0.y;
                        acc[2] += cw * u0.z; acc[3] += cw * u0.w;
                        acc[4] += cw * u1.x; acc[5] += cw * u1.y;
                        acc[6] += cw * u1.z; acc[7] += cw * u1.w;
                        s += cw;
                    }
                }
            }
        }

        float* urow = Us + q * ULD + lane * 8;
        *(float4*)(urow)     = make_float4(acc[0], acc[1], acc[2], acc[3]);
        *(float4*)(urow + 4) = make_float4(acc[4], acc[5], acc[6], acc[7]);
        if (lane == 0) sw[q] = s;
    }

    cpasync_wait0();
    __syncthreads();

    // ---- phase 2: S_tile[64,32] = U[64,256] @ B[256,32] (TF32 wmma) ----
    // warp tile 16x16: wr = warpId>>1 (4 row groups), wc = warpId&1 (2 col groups)
    int wr = wid >> 1, wc = wid & 1;
    wmma::fragment<wmma::accumulator, 16, 16, 8, float> acc;
    wmma::fill_fragment(acc, 0.0f);

    #pragma unroll
    for (int s = 0; s < 32; s++) {
        int kk = s * 8;
        wmma::fragment<wmma::matrix_a, 16, 16, 8, wmma::precision::tf32, wmma::row_major> af;
        wmma::fragment<wmma::matrix_b, 16, 16, 8, wmma::precision::tf32, wmma::row_major> bf;
        wmma::load_matrix_sync(af, Us + (wr * 16) * ULD + kk, ULD);
        #pragma unroll
        for (int e = 0; e < af.num_elements; e++)
            af.x[e] = wmma::__float_to_tf32(af.x[e]);
        wmma::load_matrix_sync(bf, Bs + kk * BLD + wc * 16, BLD);
        #pragma unroll
        for (int e = 0; e < bf.num_elements; e++)
            bf.x[e] = wmma::__float_to_tf32(bf.x[e]);
        wmma::mma_sync(acc, af, bf, acc);
    }

    __syncthreads();   // all warps done reading Us before C reuses it
    float* Cs = Us;    // reuse U region as C [64][36]
    wmma::store_matrix_sync(Cs + (wr * 16) * BLD + wc * 16, acc, BLD, wmma::mem_row_major);
    __syncthreads();

    // epilogue: 64x32 = 512 float4, 2 per thread; add sw*bv
    #pragma unroll
    for (int i = 0; i < 2; i++) {
        int f = i * 256 + tid;
        int r = f >> 3, c4 = f & 7;
        float s = sw[r];
        float4 v  = *(float4*)&Cs[r * BLD + c4 * 4];
        float4 bb = *(const float4*)(bv + h * 32 + c4 * 4);
        v.x += s * bb.x; v.y += s * bb.y; v.z += s * bb.z; v.w += s * bb.w;
        *(float4*)&g_S[(size_t)(m0 + r) * CD + h * 32 + c4 * 4] = v;
    }
}

// =====================================================================
// kernel 3: output projection GEMM, BM=64 x BN=64 (512 CTAs), 3 stages
// out[8192,256] = g_S @ Wout + bout
// =====================================================================
#define BM 64
#define BN 64
#define BK 16
#define NSTG 3
#define LDA 20
#define LDB 68
#define LDC 68

struct __align__(16) SmemGemm {
    union {
        struct { float a[NSTG][BM * LDA]; float b[NSTG][BK * LDB]; } ab;  // 27.8 KB
        float c[BM * LDC];                                                // 17.4 KB
    };
};

__global__ void __launch_bounds__(256)
k_gemmO(const float* __restrict__ Wt, const float* __restrict__ bias,
        float* __restrict__ out)
{
    __shared__ SmemGemm sm;
    const float* A = (const float*)g_S;

    int n0 = blockIdx.x * BN;
    int m0 = blockIdx.y * BM;
    int tid = threadIdx.x;
    int warpId = tid >> 5;
    int wr = warpId >> 1;              // 4 row groups of 16
    int wc = warpId & 1;               // 2 col groups of 32

    wmma::fragment<wmma::accumulator, 16, 16, 8, float> acc[2];
    wmma::fill_fragment(acc[0], 0.0f);
    wmma::fill_fragment(acc[1], 0.0f);

    auto load_tiles = [&](int buf, int k0) {
        {   // A: 64x16 = 256 f4, 1/thread
            int r = tid >> 2, c4 = tid & 3;
            cpasync16(&sm.ab.a[buf][r * LDA + c4 * 4],
                      A + (size_t)(m0 + r) * CD + k0 + c4 * 4);
        }
        {   // B: 16x64 = 256 f4, 1/thread
            int r = tid >> 4, c4 = tid & 15;
            cpasync16(&sm.ab.b[buf][r * LDB + c4 * 4],
                      Wt + (size_t)(k0 + r) * CD + n0 + c4 * 4);
        }
        cpasync_commit();
    };

    load_tiles(0, 0);
    load_tiles(1, BK);

    const int NIT = CD / BK;           // 16
    for (int it = 0; it < NIT; ++it) {
        asm volatile("cp.async.wait_group 1;");
        __syncthreads();
        if (it + 2 < NIT) load_tiles((it + 2) % NSTG, (it + 2) * BK);
        else              cpasync_commit();

        int buf = it % NSTG;
        #pragma unroll
        for (int kk = 0; kk < BK; kk += 8) {
            wmma::fragment<wmma::matrix_a, 16, 16, 8, wmma::precision::tf32, wmma::row_major> af;
            wmma::fragment<wmma::matrix_b, 16, 16, 8, wmma::precision::tf32, wmma::row_major> bf[2];
            wmma::load_matrix_sync(af, &sm.ab.a[buf][(wr * 16) * LDA + kk], LDA);
            #pragma unroll
            for (int e = 0; e < af.num_elements; e++)
                af.x[e] = wmma::__float_to_tf32(af.x[e]);
            #pragma unroll
            for (int j = 0; j < 2; j++) {
                wmma::load_matrix_sync(bf[j], &sm.ab.b[buf][kk * LDB + wc * 32 + j * 16], LDB);
                #pragma unroll
                for (int e = 0; e < bf[j].num_elements; e++)
                    bf[j].x[e] = wmma::__float_to_tf32(bf[j].x[e]);
                wmma::mma_sync(acc[j], af, bf[j], acc[j]);
            }
        }
        __syncthreads();
    }

    #pragma unroll
    for (int j = 0; j < 2; j++)
        wmma::store_matrix_sync(&sm.c[(wr * 16) * LDC + wc * 32 + j * 16],
                                acc[j], LDC, wmma::mem_row_major);
    __syncthreads();

    // 64x64 = 1024 f4, 4 per thread
    #pragma unroll
    for (int i = 0; i < 4; i++) {
        int id = i * 256 + tid;
        int r = id >> 4, c4 = id & 15;
        float4 v = *(float4*)&sm.c[r * LDC + c4 * 4];
        int col = n0 + c4 * 4;
        v.x += bias[col]; v.y += bias[col + 1]; v.z += bias[col + 2]; v.w += bias[col + 3];
        *(float4*)&out[(size_t)(m0 + r) * CD + col] = v;
    }
}

// ---------------- launch -----------------------------------------------------
extern "C" void kernel_launch(void* const* d_in, const int* in_sizes, int n_in,
                              void* d_out, int out_size)
{
    const float* query  = (const float*)d_in[0];
    const float* memory = (const float*)d_in[1];
    const float* refp   = (const float*)d_in[2];
    const float* Wv     = (const float*)d_in[3];
    const float* bv     = (const float*)d_in[4];
    const float* Woff   = (const float*)d_in[5];
    const float* boff   = (const float*)d_in[6];
    const float* Wattn  = (const float*)d_in[7];
    const float* battn  = (const float*)d_in[8];
    const float* Wout   = (const float*)d_in[9];
    const float* bout   = (const float*)d_in[10];
    float* out = (float*)d_out;

    cudaFuncSetAttribute(k_gathS, cudaFuncAttributeMaxDynamicSharedMemorySize, SMEM_F);

    // 1) offsets / attn weights / sample coordinates
    k_offsets<<<(NB * LQ) / QB, 256>>>(query, refp, Woff, boff, Wattn, battn);

    // 2) fused gather + per-head value projection -> g_S
    k_gathS<<<dim3((NB * LQ) / FBM, NH), 256, SMEM_F>>>(memory, Wv, bv);

    // 3) output projection GEMM
    k_gemmO<<<dim3(CD / BN, (NB * LQ) / BM), 256>>>(Wout, bout, out);
}

// round 13
// speedup vs baseline: 1.2542x; 1.2542x over previous
#include <cstdint>
#include <cuda_runtime.h>
#include <mma.h>

using namespace nvcuda;

// Problem constants (fixed shapes per reference setup_inputs)
#define NB   8
#define LQ   1024
#define CD   256
#define NH   8
#define NPT  4
#define HD   32
#define HH   128
#define WWp  128
#define HWSZ (HH * WWp)

// ---------------- scratch (device globals; no allocations allowed) ----------
__device__ float4 g_samp[(size_t)NB * LQ * NH * NPT];     // (x_pix, y_pix, attn_w, _)
__device__ float  g_U[(size_t)NH * NB * LQ * CD];         // gathered memory rows, head-major
__device__ float  g_sw[(size_t)NB * LQ * NH];             // sum of effective weights
__device__ float  g_S[(size_t)NB * LQ * CD];              // sampled values [bq][h*32+d]

// ---------------- cp.async helpers ------------------------------------------
__device__ __forceinline__ void cpasync16(void* smem_dst, const void* gmem_src) {
    unsigned int s = (unsigned int)__cvta_generic_to_shared(smem_dst);
    asm volatile("cp.async.cg.shared.global [%0], [%1], 16;" :: "r"(s), "l"(gmem_src));
}
__device__ __forceinline__ void cpasync_commit() {
    asm volatile("cp.async.commit_group;");
}
__device__ __forceinline__ void cpasync_wait0() {
    asm volatile("cp.async.wait_group 0;");
}

// =====================================================================
// kernel 1: offsets + attn weights + sample coords, 16 queries per block
// (512 blocks -> ~3.5 CTA/SM; was 256 blocks / 1.7 CTA/SM, grid-limited)
// =====================================================================
#define QB 16
__global__ void __launch_bounds__(256) k_offsets(
    const float* __restrict__ query,
    const float* __restrict__ refp,
    const float* __restrict__ Woff, const float* __restrict__ boff,
    const float* __restrict__ Wattn, const float* __restrict__ battn)
{
    __shared__ float sq[QB][CD + 4];   // 16.6 KB
    __shared__ float sp[QB][96 + 2];   // 6.3 KB

    int q0  = blockIdx.x * QB;
    int tid = threadIdx.x;

    // load 16 query rows (1024 float4, 4 per thread)
    #pragma unroll
    for (int i = 0; i < 4; i++) {
        int id = i * 256 + tid;
        int q = id >> 6, c4 = id & 63;
        float4 v = *(const float4*)(query + (size_t)(q0 + q) * CD + c4 * 4);
        *(float4*)&sq[q][c4 * 4] = v;
    }
    __syncthreads();

    // GEMV: warp qg handles queries {qg, qg+8}; lane j0 computes cols {j0, 32+j0, attn j0}
    {
        int j0 = tid & 31;
        int qg = tid >> 5;
        float a0[2], a1[2], a2[2];
        #pragma unroll
        for (int m = 0; m < 2; m++) {
            a0[m] = boff[j0];
            a1[m] = boff[j0 + 32];
            a2[m] = battn[j0];
        }
        #pragma unroll 8
        for (int k = 0; k < CD; k++) {
            float w0 = Woff[k * 64 + j0];
            float w1 = Woff[k * 64 + 32 + j0];
            float w2 = Wattn[k * 32 + j0];
            #pragma unroll
            for (int m = 0; m < 2; m++) {
                float s = sq[qg + 8 * m][k];   // broadcast within warp
                a0[m] += w0 * s;
                a1[m] += w1 * s;
                a2[m] += w2 * s;
            }
        }
        #pragma unroll
        for (int m = 0; m < 2; m++) {
            sp[qg + 8 * m][j0]      = a0[m];
            sp[qg + 8 * m][32 + j0] = a1[m];
            sp[qg + 8 * m][64 + j0] = a2[m];
        }
    }
    __syncthreads();

    // finalize: 16*32 = 512 items, 2 per thread
    #pragma unroll
    for (int i = 0; i < 2; i++) {
        int item = i * 256 + tid;
        int q = item >> 5, t32 = item & 31;
        int h = t32 >> 2, p = t32 & 3;

        float l0 = sp[q][64 + h * 4 + 0], l1 = sp[q][64 + h * 4 + 1];
        float l2 = sp[q][64 + h * 4 + 2], l3 = sp[q][64 + h * 4 + 3];
        float m  = fmaxf(fmaxf(l0, l1), fmaxf(l2, l3));
        float e0 = __expf(l0 - m), e1 = __expf(l1 - m);
        float e2 = __expf(l2 - m), e3 = __expf(l3 - m);
        float inv = 1.0f / (e0 + e1 + e2 + e3);
        float ep  = (p == 0) ? e0 : (p == 1) ? e1 : (p == 2) ? e2 : e3;
        float w   = ep * inv;

        int bq = q0 + q;
        float refx = refp[bq * 2 + 0];
        float refy = refp[bq * 2 + 1];
        float ox = sp[q][(h * NPT + p) * 2 + 0];
        float oy = sp[q][(h * NPT + p) * 2 + 1];
        // grid_sample align_corners=False: pix = (ref + off/Dim)*Dim - 0.5
        float x = refx * (float)WWp + ox - 0.5f;
        float y = refy * (float)HH  + oy - 0.5f;
        g_samp[(size_t)bq * (NH * NPT) + t32] = make_float4(x, y, w, 0.f);
    }
}

// =====================================================================
// kernel 2: weighted gather of RAW memory rows (R11 version, measured good:
// block = query -> all 8 heads share the L1-hot pixel neighborhood)
// =====================================================================
__global__ void __launch_bounds__(256) k_gather(const float* __restrict__ memory)
{
    int bq   = blockIdx.x;
    int h    = threadIdx.x >> 5;
    int lane = threadIdx.x & 31;
    int b    = bq >> 10;

    const float* mb = memory + (size_t)b * HWSZ * CD + lane * 8;

    float acc[8] = {0.f, 0.f, 0.f, 0.f, 0.f, 0.f, 0.f, 0.f};
    float s = 0.f;

    #pragma unroll
    for (int p = 0; p < NPT; p++) {
        float4 sm = g_samp[(size_t)bq * (NH * NPT) + h * NPT + p];
        float x = sm.x, y = sm.y, w = sm.z;
        float xf = floorf(x), yf = floorf(y);
        int ix = (int)xf, iy = (int)yf;
        float fx = x - xf, fy = y - yf;
        float w00 = w * (1.0f - fy) * (1.0f - fx);
        float w01 = w * (1.0f - fy) * fx;
        float w10 = w * fy * (1.0f - fx);
        float w11 = w * fy * fx;

        if ((unsigned)ix < (WWp - 1) && (unsigned)iy < (HH - 1)) {
            const float* c00 = mb + (size_t)(iy * WWp + ix) * CD;
            float4 a0 = *(const float4*)(c00);
            float4 a1 = *(const float4*)(c00 + 4);
            float4 b0 = *(const float4*)(c00 + CD);
            float4 b1 = *(const float4*)(c00 + CD + 4);
            float4 c0 = *(const float4*)(c00 + WWp * CD);
            float4 c1 = *(const float4*)(c00 + WWp * CD + 4);
            float4 d0 = *(const float4*)(c00 + WWp * CD + CD);
            float4 d1 = *(const float4*)(c00 + WWp * CD + CD + 4);
            acc[0] += w00 * a0.x + w01 * b0.x + w10 * c0.x + w11 * d0.x;
            acc[1] += w00 * a0.y + w01 * b0.y + w10 * c0.y + w11 * d0.y;
            acc[2] += w00 * a0.z + w01 * b0.z + w10 * c0.z + w11 * d0.z;
            acc[3] += w00 * a0.w + w01 * b0.w + w10 * c0.w + w11 * d0.w;
            acc[4] += w00 * a1.x + w01 * b1.x + w10 * c1.x + w11 * d1.x;
            acc[5] += w00 * a1.y + w01 * b1.y + w10 * c1.y + w11 * d1.y;
            acc[6] += w00 * a1.z + w01 * b1.z + w10 * c1.z + w11 * d1.z;
            acc[7] += w00 * a1.w + w01 * b1.w + w10 * c1.w + w11 * d1.w;
            s += w;
        } else {
            #pragma unroll
            for (int cy = 0; cy < 2; cy++) {
                int yy = iy + cy;
                if ((unsigned)yy >= HH) continue;
                #pragma unroll
                for (int cx = 0; cx < 2; cx++) {
                    int xx = ix + cx;
                    if ((unsigned)xx >= WWp) continue;
                    float cw = cy ? (cx ? w11 : w10) : (cx ? w01 : w00);
                    const float* cp = mb + (size_t)(yy * WWp + xx) * CD;
                    float4 u0 = *(const float4*)(cp);
                    float4 u1 = *(const float4*)(cp + 4);
                    acc[0] += cw * u0.x; acc[1] += cw * u0.y;
                    acc[2] += cw * u0.z; acc[3] += cw * u0.w;
                    acc[4] += cw * u1.x; acc[5] += cw * u1.y;
                    acc[6] += cw * u1.z; acc[7] += cw * u1.w;
                    s += cw;
                }
            }
        }
    }

    float* urow = g_U + ((size_t)h * (NB * LQ) + bq) * CD + lane * 8;
    *(float4*)(urow)     = make_float4(acc[0], acc[1], acc[2], acc[3]);
    *(float4*)(urow + 4) = make_float4(acc[4], acc[5], acc[6], acc[7]);
    if (lane == 0) g_sw[(size_t)bq * NH + h] = s;
}

// =====================================================================
// kernel 3: per-head value projection on gathered rows (R11 version)
// =====================================================================
#define SBM 128
#define SBN 32
#define SBK 16
#define SLDA 20
#define SLDB 36
#define SLDC 36

struct __align__(16) SmemS {
    union {
        struct { float a[2][SBM * SLDA]; float b[2][SBK * SLDB]; } ab;
        float c[SBM * SLDC];
    };
};

__global__ void __launch_bounds__(256)
k_gemmS(const float* __restrict__ Wv, const float* __restrict__ bv)
{
    __shared__ SmemS sm;
    int h   = blockIdx.y;
    int m0  = blockIdx.x * SBM;
    int tid = threadIdx.x;
    int warpId = tid >> 5;

    const float* A = g_U + (size_t)h * (NB * LQ) * CD;

    wmma::fragment<wmma::accumulator, 16, 16, 8, float> acc[2];
    wmma::fill_fragment(acc[0], 0.0f);
    wmma::fill_fragment(acc[1], 0.0f);

    auto load_tiles = [&](int buf, int k0) {
        #pragma unroll
        for (int i = 0; i < 2; i++) {
            int f4 = tid + i * 256;
            int r = f4 >> 2, c4 = f4 & 3;
            cpasync16(&sm.ab.a[buf][r * SLDA + c4 * 4],
                      A + (size_t)(m0 + r) * CD + k0 + c4 * 4);
        }
        if (tid < 128) {
            int r = tid >> 3, c4 = tid & 7;
            cpasync16(&sm.ab.b[buf][r * SLDB + c4 * 4],
                      Wv + (size_t)(k0 + r) * CD + h * 32 + c4 * 4);
        }
        cpasync_commit();
    };

    load_tiles(0, 0);

    const int NIT = CD / SBK;
    for (int it = 0; it < NIT; ++it) {
        cpasync_wait0();
        __syncthreads();
        if (it + 1 < NIT) load_tiles((it + 1) & 1, (it + 1) * SBK);

        int buf = it & 1;
        #pragma unroll
        for (int kk = 0; kk < SBK; kk += 8) {
            wmma::fragment<wmma::matrix_a, 16, 16, 8, wmma::precision::tf32, wmma::row_major> af;
            wmma::fragment<wmma::matrix_b, 16, 16, 8, wmma::precision::tf32, wmma::row_major> bf[2];
            wmma::load_matrix_sync(af, &sm.ab.a[buf][(warpId * 16) * SLDA + kk], SLDA);
            #pragma unroll
            for (int e = 0; e < af.num_elements; e++)
                af.x[e] = wmma::__float_to_tf32(af.x[e]);
            #pragma unroll
            for (int j = 0; j < 2; j++) {
                wmma::load_matrix_sync(bf[j], &sm.ab.b[buf][kk * SLDB + j * 16], SLDB);
                #pragma unroll
                for (int e = 0; e < bf[j].num_elements; e++)
                    bf[j].x[e] = wmma::__float_to_tf32(bf[j].x[e]);
                wmma::mma_sync(acc[j], af, bf[j], acc[j]);
            }
        }
        __syncthreads();
    }

    #pragma unroll
    for (int j = 0; j < 2; j++)
        wmma::store_matrix_sync(&sm.c[(warpId * 16) * SLDC + j * 16], acc[j],
                                SLDC, wmma::mem_row_major);
    __syncthreads();

    #pragma unroll
    for (int i = 0; i < 4; i++) {
        int f4 = i * 256 + tid;
        int r = f4 >> 3, c4 = f4 & 7;
        float s = g_sw[(size_t)(m0 + r) * NH + h];
        float4 v  = *(float4*)&sm.c[r * SLDC + c4 * 4];
        float4 bb = *(const float4*)(bv + h * 32 + c4 * 4);
        v.x += s * bb.x; v.y += s * bb.y; v.z += s * bb.z; v.w += s * bb.w;
        *(float4*)&g_S[(size_t)(m0 + r) * CD + h * 32 + c4 * 4] = v;
    }
}

// =====================================================================
// kernel 4: output projection GEMM, BM=64 x BN=64 (512 CTAs), 3 stages
// =====================================================================
#define BM 64
#define BN 64
#define BK 16
#define NSTG 3
#define LDA 20
#define LDB 68
#define LDC 68

struct __align__(16) SmemGemm {
    union {
        struct { float a[NSTG][BM * LDA]; float b[NSTG][BK * LDB]; } ab;
        float c[BM * LDC];
    };
};

__global__ void __launch_bounds__(256)
k_gemmO(const float* __restrict__ Wt, const float* __restrict__ bias,
        float* __restrict__ out)
{
    __shared__ SmemGemm sm;
    const float* A = (const float*)g_S;

    int n0 = blockIdx.x * BN;
    int m0 = blockIdx.y * BM;
    int tid = threadIdx.x;
    int warpId = tid >> 5;
    int wr = warpId >> 1;              // 4 row groups of 16
    int wc = warpId & 1;               // 2 col groups of 32

    wmma::fragment<wmma::accumulator, 16, 16, 8, float> acc[2];
    wmma::fill_fragment(acc[0], 0.0f);
    wmma::fill_fragment(acc[1], 0.0f);

    auto load_tiles = [&](int buf, int k0) {
        {   // A: 64x16 = 256 f4, 1/thread
            int r = tid >> 2, c4 = tid & 3;
            cpasync16(&sm.ab.a[buf][r * LDA + c4 * 4],
                      A + (size_t)(m0 + r) * CD + k0 + c4 * 4);
        }
        {   // B: 16x64 = 256 f4, 1/thread
            int r = tid >> 4, c4 = tid & 15;
            cpasync16(&sm.ab.b[buf][r * LDB + c4 * 4],
                      Wt + (size_t)(k0 + r) * CD + n0 + c4 * 4);
        }
        cpasync_commit();
    };

    load_tiles(0, 0);
    load_tiles(1, BK);

    const int NIT = CD / BK;           // 16
    for (int it = 0; it < NIT; ++it) {
        asm volatile("cp.async.wait_group 1;");
        __syncthreads();
        if (it + 2 < NIT) load_tiles((it + 2) % NSTG, (it + 2) * BK);
        else              cpasync_commit();

        int buf = it % NSTG;
        #pragma unroll
        for (int kk = 0; kk < BK; kk += 8) {
            wmma::fragment<wmma::matrix_a, 16, 16, 8, wmma::precision::tf32, wmma::row_major> af;
            wmma::fragment<wmma::matrix_b, 16, 16, 8, wmma::precision::tf32, wmma::row_major> bf[2];
            wmma::load_matrix_sync(af, &sm.ab.a[buf][(wr * 16) * LDA + kk], LDA);
            #pragma unroll
            for (int e = 0; e < af.num_elements; e++)
                af.x[e] = wmma::__float_to_tf32(af.x[e]);
            #pragma unroll
            for (int j = 0; j < 2; j++) {
                wmma::load_matrix_sync(bf[j], &sm.ab.b[buf][kk * LDB + wc * 32 + j * 16], LDB);
                #pragma unroll
                for (int e = 0; e < bf[j].num_elements; e++)
                    bf[j].x[e] = wmma::__float_to_tf32(bf[j].x[e]);
                wmma::mma_sync(acc[j], af, bf[j], acc[j]);
            }
        }
        __syncthreads();
    }

    #pragma unroll
    for (int j = 0; j < 2; j++)
        wmma::store_matrix_sync(&sm.c[(wr * 16) * LDC + wc * 32 + j * 16],
                                acc[j], LDC, wmma::mem_row_major);
    __syncthreads();

    #pragma unroll
    for (int i = 0; i < 4; i++) {
        int id = i * 256 + tid;
        int r = id >> 4, c4 = id & 15;
        float4 v = *(float4*)&sm.c[r * LDC + c4 * 4];
        int col = n0 + c4 * 4;
        v.x += bias[col]; v.y += bias[col + 1]; v.z += bias[col + 2]; v.w += bias[col + 3];
        *(float4*)&out[(size_t)(m0 + r) * CD + col] = v;
    }
}

// ---------------- launch -----------------------------------------------------
extern "C" void kernel_launch(void* const* d_in, const int* in_sizes, int n_in,
                              void* d_out, int out_size)
{
    const float* query  = (const float*)d_in[0];
    const float* memory = (const float*)d_in[1];
    const float* refp   = (const float*)d_in[2];
    const float* Wv     = (const float*)d_in[3];
    const float* bv     = (const float*)d_in[4];
    const float* Woff   = (const float*)d_in[5];
    const float* boff   = (const float*)d_in[6];
    const float* Wattn  = (const float*)d_in[7];
    const float* battn  = (const float*)d_in[8];
    const float* Wout   = (const float*)d_in[9];
    const float* bout   = (const float*)d_in[10];
    float* out = (float*)d_out;

    // 1) offsets / attn weights / sample coordinates (512 blocks)
    k_offsets<<<(NB * LQ) / QB, 256>>>(query, refp, Woff, boff, Wattn, battn);

    // 2) weighted gather of raw memory rows (block = query, heads share L1)
    k_gather<<<NB * LQ, 256>>>(memory);

    // 3) per-head value projection on gathered rows (+ s*bv bias term)
    k_gemmS<<<dim3((NB * LQ) / SBM, NH), 256>>>(Wv, bv);

    // 4) output projection GEMM (512 CTAs)
    k_gemmO<<<dim3(CD / BN, (NB * LQ) / BM), 256>>>(Wout, bout, out);
}

// round 14
// speedup vs baseline: 1.3572x; 1.0821x over previous
#include <cstdint>
#include <cuda_runtime.h>
#include <mma.h>

using namespace nvcuda;

// Problem constants (fixed shapes per reference setup_inputs)
#define NB   8
#define LQ   1024
#define CD   256
#define NH   8
#define NPT  4
#define HD   32
#define HH   128
#define WWp  128
#define HWSZ (HH * WWp)

// ---------------- scratch (device globals; no allocations allowed) ----------
__device__ float4 g_samp[(size_t)NB * LQ * NH * NPT];     // (x_pix, y_pix, attn_w, _)
__device__ float  g_U[(size_t)NH * NB * LQ * CD];         // gathered memory rows, head-major
__device__ float  g_sw[(size_t)NB * LQ * NH];             // sum of effective weights
__device__ float  g_S[(size_t)NB * LQ * CD];              // sampled values [bq][h*32+d]

// ---------------- cp.async helpers ------------------------------------------
__device__ __forceinline__ void cpasync16(void* smem_dst, const void* gmem_src) {
    unsigned int s = (unsigned int)__cvta_generic_to_shared(smem_dst);
    asm volatile("cp.async.cg.shared.global [%0], [%1], 16;" :: "r"(s), "l"(gmem_src));
}
__device__ __forceinline__ void cpasync_commit() {
    asm volatile("cp.async.commit_group;");
}
__device__ __forceinline__ void cpasync_wait0() {
    asm volatile("cp.async.wait_group 0;");
}

// =====================================================================
// kernel 1: offsets + attn weights + sample coords.
// 128 threads, 16 queries per block (512 blocks), ILP=4 preserved:
// warp qg handles queries {qg, qg+4, qg+8, qg+12}.
// =====================================================================
#define QB 16
__global__ void __launch_bounds__(128) k_offsets(
    const float* __restrict__ query,
    const float* __restrict__ refp,
    const float* __restrict__ Woff, const float* __restrict__ boff,
    const float* __restrict__ Wattn, const float* __restrict__ battn)
{
    __shared__ float sq[QB][CD + 4];   // 16.6 KB
    __shared__ float sp[QB][96 + 2];   // 6.3 KB

    int q0  = blockIdx.x * QB;
    int tid = threadIdx.x;             // 128

    // load 16 query rows (1024 float4, 8 per thread)
    #pragma unroll
    for (int i = 0; i < 8; i++) {
        int id = i * 128 + tid;
        int q = id >> 6, c4 = id & 63;
        float4 v = *(const float4*)(query + (size_t)(q0 + q) * CD + c4 * 4);
        *(float4*)&sq[q][c4 * 4] = v;
    }
    __syncthreads();

    // GEMV: warp qg (0..3) handles queries {qg, qg+4, qg+8, qg+12};
    // lane j0 computes cols {j0, 32+j0 (offsets), j0 (attn)} -> 4-wide ILP
    {
        int j0 = tid & 31;
        int qg = tid >> 5;
        float a0[4], a1[4], a2[4];
        #pragma unroll
        for (int m = 0; m < 4; m++) {
            a0[m] = boff[j0];
            a1[m] = boff[j0 + 32];
            a2[m] = battn[j0];
        }
        #pragma unroll 8
        for (int k = 0; k < CD; k++) {
            float w0 = Woff[k * 64 + j0];
            float w1 = Woff[k * 64 + 32 + j0];
            float w2 = Wattn[k * 32 + j0];
            #pragma unroll
            for (int m = 0; m < 4; m++) {
                float s = sq[qg + 4 * m][k];   // broadcast within warp
                a0[m] += w0 * s;
                a1[m] += w1 * s;
                a2[m] += w2 * s;
            }
        }
        #pragma unroll
        for (int m = 0; m < 4; m++) {
            sp[qg + 4 * m][j0]      = a0[m];
            sp[qg + 4 * m][32 + j0] = a1[m];
            sp[qg + 4 * m][64 + j0] = a2[m];
        }
    }
    __syncthreads();

    // finalize: 16*32 = 512 items, 4 per thread
    #pragma unroll
    for (int i = 0; i < 4; i++) {
        int item = i * 128 + tid;
        int q = item >> 5, t32 = item & 31;
        int h = t32 >> 2, p = t32 & 3;

        float l0 = sp[q][64 + h * 4 + 0], l1 = sp[q][64 + h * 4 + 1];
        float l2 = sp[q][64 + h * 4 + 2], l3 = sp[q][64 + h * 4 + 3];
        float m  = fmaxf(fmaxf(l0, l1), fmaxf(l2, l3));
        float e0 = __expf(l0 - m), e1 = __expf(l1 - m);
        float e2 = __expf(l2 - m), e3 = __expf(l3 - m);
        float inv = 1.0f / (e0 + e1 + e2 + e3);
        float ep  = (p == 0) ? e0 : (p == 1) ? e1 : (p == 2) ? e2 : e3;
        float w   = ep * inv;

        int bq = q0 + q;
        float refx = refp[bq * 2 + 0];
        float refy = refp[bq * 2 + 1];
        float ox = sp[q][(h * NPT + p) * 2 + 0];
        float oy = sp[q][(h * NPT + p) * 2 + 1];
        // grid_sample align_corners=False: pix = (ref + off/Dim)*Dim - 0.5
        float x = refx * (float)WWp + ox - 0.5f;
        float y = refy * (float)HH  + oy - 0.5f;
        g_samp[(size_t)bq * (NH * NPT) + t32] = make_float4(x, y, w, 0.f);
    }
}

// =====================================================================
// kernel 2: weighted gather of RAW memory rows (R11 version, measured good:
// block = query -> all 8 heads share the L1-hot pixel neighborhood)
// =====================================================================
__global__ void __launch_bounds__(256) k_gather(const float* __restrict__ memory)
{
    int bq   = blockIdx.x;
    int h    = threadIdx.x >> 5;
    int lane = threadIdx.x & 31;
    int b    = bq >> 10;

    const float* mb = memory + (size_t)b * HWSZ * CD + lane * 8;

    float acc[8] = {0.f, 0.f, 0.f, 0.f, 0.f, 0.f, 0.f, 0.f};
    float s = 0.f;

    #pragma unroll
    for (int p = 0; p < NPT; p++) {
        float4 sm = g_samp[(size_t)bq * (NH * NPT) + h * NPT + p];
        float x = sm.x, y = sm.y, w = sm.z;
        float xf = floorf(x), yf = floorf(y);
        int ix = (int)xf, iy = (int)yf;
        float fx = x - xf, fy = y - yf;
        float w00 = w * (1.0f - fy) * (1.0f - fx);
        float w01 = w * (1.0f - fy) * fx;
        float w10 = w * fy * (1.0f - fx);
        float w11 = w * fy * fx;

        if ((unsigned)ix < (WWp - 1) && (unsigned)iy < (HH - 1)) {
            const float* c00 = mb + (size_t)(iy * WWp + ix) * CD;
            float4 a0 = *(const float4*)(c00);
            float4 a1 = *(const float4*)(c00 + 4);
            float4 b0 = *(const float4*)(c00 + CD);
            float4 b1 = *(const float4*)(c00 + CD + 4);
            float4 c0 = *(const float4*)(c00 + WWp * CD);
            float4 c1 = *(const float4*)(c00 + WWp * CD + 4);
            float4 d0 = *(const float4*)(c00 + WWp * CD + CD);
            float4 d1 = *(const float4*)(c00 + WWp * CD + CD + 4);
            acc[0] += w00 * a0.x + w01 * b0.x + w10 * c0.x + w11 * d0.x;
            acc[1] += w00 * a0.y + w01 * b0.y + w10 * c0.y + w11 * d0.y;
            acc[2] += w00 * a0.z + w01 * b0.z + w10 * c0.z + w11 * d0.z;
            acc[3] += w00 * a0.w + w01 * b0.w + w10 * c0.w + w11 * d0.w;
            acc[4] += w00 * a1.x + w01 * b1.x + w10 * c1.x + w11 * d1.x;
            acc[5] += w00 * a1.y + w01 * b1.y + w10 * c1.y + w11 * d1.y;
            acc[6] += w00 * a1.z + w01 * b1.z + w10 * c1.z + w11 * d1.z;
            acc[7] += w00 * a1.w + w01 * b1.w + w10 * c1.w + w11 * d1.w;
            s += w;
        } else {
            #pragma unroll
            for (int cy = 0; cy < 2; cy++) {
                int yy = iy + cy;
                if ((unsigned)yy >= HH) continue;
                #pragma unroll
                for (int cx = 0; cx < 2; cx++) {
                    int xx = ix + cx;
                    if ((unsigned)xx >= WWp) continue;
                    float cw = cy ? (cx ? w11 : w10) : (cx ? w01 : w00);
                    const float* cp = mb + (size_t)(yy * WWp + xx) * CD;
                    float4 u0 = *(const float4*)(cp);
                    float4 u1 = *(const float4*)(cp + 4);
                    acc[0] += cw * u0.x; acc[1] += cw * u0.y;
                    acc[2] += cw * u0.z; acc[3] += cw * u0.w;
                    acc[4] += cw * u1.x; acc[5] += cw * u1.y;
                    acc[6] += cw * u1.z; acc[7] += cw * u1.w;
                    s += cw;
                }
            }
        }
    }

    float* urow = g_U + ((size_t)h * (NB * LQ) + bq) * CD + lane * 8;
    *(float4*)(urow)     = make_float4(acc[0], acc[1], acc[2], acc[3]);
    *(float4*)(urow + 4) = make_float4(acc[4], acc[5], acc[6], acc[7]);
    if (lane == 0) g_sw[(size_t)bq * NH + h] = s;
}

// =====================================================================
// kernel 3: per-head value projection on gathered rows (R11 version)
// =====================================================================
#define SBM 128
#define SBN 32
#define SBK 16
#define SLDA 20
#define SLDB 36
#define SLDC 36

struct __align__(16) SmemS {
    union {
        struct { float a[2][SBM * SLDA]; float b[2][SBK * SLDB]; } ab;
        float c[SBM * SLDC];
    };
};

__global__ void __launch_bounds__(256)
k_gemmS(const float* __restrict__ Wv, const float* __restrict__ bv)
{
    __shared__ SmemS sm;
    int h   = blockIdx.y;
    int m0  = blockIdx.x * SBM;
    int tid = threadIdx.x;
    int warpId = tid >> 5;

    const float* A = g_U + (size_t)h * (NB * LQ) * CD;

    wmma::fragment<wmma::accumulator, 16, 16, 8, float> acc[2];
    wmma::fill_fragment(acc[0], 0.0f);
    wmma::fill_fragment(acc[1], 0.0f);

    auto load_tiles = [&](int buf, int k0) {
        #pragma unroll
        for (int i = 0; i < 2; i++) {
            int f4 = tid + i * 256;
            int r = f4 >> 2, c4 = f4 & 3;
            cpasync16(&sm.ab.a[buf][r * SLDA + c4 * 4],
                      A + (size_t)(m0 + r) * CD + k0 + c4 * 4);
        }
        if (tid < 128) {
            int r = tid >> 3, c4 = tid & 7;
            cpasync16(&sm.ab.b[buf][r * SLDB + c4 * 4],
                      Wv + (size_t)(k0 + r) * CD + h * 32 + c4 * 4);
        }
        cpasync_commit();
    };

    load_tiles(0, 0);

    const int NIT = CD / SBK;
    for (int it = 0; it < NIT; ++it) {
        cpasync_wait0();
        __syncthreads();
        if (it + 1 < NIT) load_tiles((it + 1) & 1, (it + 1) * SBK);

        int buf = it & 1;
        #pragma unroll
        for (int kk = 0; kk < SBK; kk += 8) {
            wmma::fragment<wmma::matrix_a, 16, 16, 8, wmma::precision::tf32, wmma::row_major> af;
            wmma::fragment<wmma::matrix_b, 16, 16, 8, wmma::precision::tf32, wmma::row_major> bf[2];
            wmma::load_matrix_sync(af, &sm.ab.a[buf][(warpId * 16) * SLDA + kk], SLDA);
            #pragma unroll
            for (int e = 0; e < af.num_elements; e++)
                af.x[e] = wmma::__float_to_tf32(af.x[e]);
            #pragma unroll
            for (int j = 0; j < 2; j++) {
                wmma::load_matrix_sync(bf[j], &sm.ab.b[buf][kk * SLDB + j * 16], SLDB);
                #pragma unroll
                for (int e = 0; e < bf[j].num_elements; e++)
                    bf[j].x[e] = wmma::__float_to_tf32(bf[j].x[e]);
                wmma::mma_sync(acc[j], af, bf[j], acc[j]);
            }
        }
        __syncthreads();
    }

    #pragma unroll
    for (int j = 0; j < 2; j++)
        wmma::store_matrix_sync(&sm.c[(warpId * 16) * SLDC + j * 16], acc[j],
                                SLDC, wmma::mem_row_major);
    __syncthreads();

    #pragma unroll
    for (int i = 0; i < 4; i++) {
        int f4 = i * 256 + tid;
        int r = f4 >> 3, c4 = f4 & 7;
        float s = g_sw[(size_t)(m0 + r) * NH + h];
        float4 v  = *(float4*)&sm.c[r * SLDC + c4 * 4];
        float4 bb = *(const float4*)(bv + h * 32 + c4 * 4);
        v.x += s * bb.x; v.y += s * bb.y; v.z += s * bb.z; v.w += s * bb.w;
        *(float4*)&g_S[(size_t)(m0 + r) * CD + h * 32 + c4 * 4] = v;
    }
}

// =====================================================================
// kernel 4: output projection GEMM (R11 version: BM=128 x BN=64, 3 stages)
// =====================================================================
#define BM 128
#define BN 64
#define BK 16
#define NSTG 3
#define LDA 20
#define LDB 68
#define LDC 68

struct __align__(16) SmemGemm {
    union {
        struct { float a[NSTG][BM * LDA]; float b[NSTG][BK * LDB]; } ab;
        float c[BM * LDC];
    };
};

__global__ void __launch_bounds__(256)
k_gemmO(const float* __restrict__ Wt, const float* __restrict__ bias,
        float* __restrict__ out)
{
    __shared__ SmemGemm sm;
    const float* A = (const float*)g_S;

    int n0 = blockIdx.x * BN;
    int m0 = blockIdx.y * BM;
    int tid = threadIdx.x;
    int warpId = tid >> 5;
    int wr = warpId >> 1;
    int wc = warpId & 1;

    wmma::fragment<wmma::accumulator, 16, 16, 8, float> acc[2][2];
    #pragma unroll
    for (int i = 0; i < 2; i++)
        #pragma unroll
        for (int j = 0; j < 2; j++) wmma::fill_fragment(acc[i][j], 0.0f);

    auto load_tiles = [&](int buf, int k0) {
        #pragma unroll
        for (int i = 0; i < 2; i++) {
            int f4 = tid + i * 256;
            int r = f4 >> 2, c4 = f4 & 3;
            cpasync16(&sm.ab.a[buf][r * LDA + c4 * 4],
                      A + (size_t)(m0 + r) * CD + k0 + c4 * 4);
        }
        {
            int r = tid >> 4, c4 = tid & 15;
            cpasync16(&sm.ab.b[buf][r * LDB + c4 * 4],
                      Wt + (size_t)(k0 + r) * CD + n0 + c4 * 4);
        }
        cpasync_commit();
    };

    load_tiles(0, 0);
    load_tiles(1, BK);

    const int NIT = CD / BK;
    for (int it = 0; it < NIT; ++it) {
        asm volatile("cp.async.wait_group 1;");
        __syncthreads();
        if (it + 2 < NIT) load_tiles((it + 2) % NSTG, (it + 2) * BK);
        else              cpasync_commit();

        int buf = it % NSTG;
        #pragma unroll
        for (int kk = 0; kk < BK; kk += 8) {
            wmma::fragment<wmma::matrix_a, 16, 16, 8, wmma::precision::tf32, wmma::row_major> af[2];
            wmma::fragment<wmma::matrix_b, 16, 16, 8, wmma::precision::tf32, wmma::row_major> bf[2];
            #pragma unroll
            for (int i = 0; i < 2; i++) {
                wmma::load_matrix_sync(af[i], &sm.ab.a[buf][(wr * 32 + i * 16) * LDA + kk], LDA);
                #pragma unroll
                for (int e = 0; e < af[i].num_elements; e++)
                    af[i].x[e] = wmma::__float_to_tf32(af[i].x[e]);
            }
            #pragma unroll
            for (int j = 0; j < 2; j++) {
                wmma::load_matrix_sync(bf[j], &sm.ab.b[buf][kk * LDB + wc * 32 + j * 16], LDB);
                #pragma unroll
                for (int e = 0; e < bf[j].num_elements; e++)
                    bf[j].x[e] = wmma::__float_to_tf32(bf[j].x[e]);
            }
            #pragma unroll
            for (int i = 0; i < 2; i++)
                #pragma unroll
                for (int j = 0; j < 2; j++)
                    wmma::mma_sync(acc[i][j], af[i], bf[j], acc[i][j]);
        }
        __syncthreads();
    }

    #pragma unroll
    for (int i = 0; i < 2; i++)
        #pragma unroll
        for (int j = 0; j < 2; j++)
            wmma::store_matrix_sync(&sm.c[(wr * 32 + i * 16) * LDC + wc * 32 + j * 16],
                                    acc[i][j], LDC, wmma::mem_row_major);
    __syncthreads();

    #pragma unroll
    for (int i = 0; i < 8; i++) {
        int id = i * 256 + tid;
        int r = id >> 4, c4 = id & 15;
        float4 v = *(float4*)&sm.c[r * LDC + c4 * 4];
        int col = n0 + c4 * 4;
        v.x += bias[col]; v.y += bias[col + 1]; v.z += bias[col + 2]; v.w += bias[col + 3];
        *(float4*)&out[(size_t)(m0 + r) * CD + col] = v;
    }
}

// ---------------- launch -----------------------------------------------------
extern "C" void kernel_launch(void* const* d_in, const int* in_sizes, int n_in,
                              void* d_out, int out_size)
{
    const float* query  = (const float*)d_in[0];
    const float* memory = (const float*)d_in[1];
    const float* refp   = (const float*)d_in[2];
    const float* Wv     = (const float*)d_in[3];
    const float* bv     = (const float*)d_in[4];
    const float* Woff   = (const float*)d_in[5];
    const float* boff   = (const float*)d_in[6];
    const float* Wattn  = (const float*)d_in[7];
    const float* battn  = (const float*)d_in[8];
    const float* Wout   = (const float*)d_in[9];
    const float* bout   = (const float*)d_in[10];
    float* out = (float*)d_out;

    // 1) offsets / attn weights / sample coordinates (512 blocks, ILP=4)
    k_offsets<<<(NB * LQ) / QB, 128>>>(query, refp, Woff, boff, Wattn, battn);

    // 2) weighted gather of raw memory rows (block = query, heads share L1)
    k_gather<<<NB * LQ, 256>>>(memory);

    // 3) per-head value projection on gathered rows (+ s*bv bias term)
    k_gemmS<<<dim3((NB * LQ) / SBM, NH), 256>>>(Wv, bv);

    // 4) output projection GEMM
    k_gemmO<<<dim3(CD / BN, (NB * LQ) / BM), 256>>>(Wout, bout, out);
}

// round 15
// speedup vs baseline: 1.5982x; 1.1776x over previous
#include <cstdint>
#include <cuda_runtime.h>
#include <mma.h>

using namespace nvcuda;

// Problem constants (fixed shapes per reference setup_inputs)
#define NB   8
#define LQ   1024
#define CD   256
#define NH   8
#define NPT  4
#define HD   32
#define HH   128
#define WWp  128
#define HWSZ (HH * WWp)
#define NQ   (NB * LQ)      // 8192

// ---------------- scratch (device globals; no allocations allowed) ----------
__device__ float4 g_samp[(size_t)NQ * NH * NPT];      // (x_pix, y_pix, attn_w, _)
__device__ float  g_U[(size_t)NH * NQ * CD];          // gathered rows (tf32-rounded)
__device__ float  g_sw[(size_t)NQ * NH];              // sum of effective weights
__device__ float  g_S[(size_t)NQ * CD];               // sampled values (tf32-rounded)
__device__ float  g_P[(size_t)NQ * 96];               // offsets(64) | attn logits(32)
__device__ float  g_Wvr[CD * CD];                     // tf32-rounded Wv
__device__ float  g_Wor[CD * CD];                     // tf32-rounded Wout
__device__ float  g_Wq[CD * 96];                      // tf32-rounded [Woff | Wattn]

// ---------------- cp.async helpers ------------------------------------------
__device__ __forceinline__ void cpasync16(void* smem_dst, const void* gmem_src) {
    unsigned int s = (unsigned int)__cvta_generic_to_shared(smem_dst);
    asm volatile("cp.async.cg.shared.global [%0], [%1], 16;" :: "r"(s), "l"(gmem_src));
}
__device__ __forceinline__ void cpasync_commit() {
    asm volatile("cp.async.commit_group;");
}
__device__ __forceinline__ void cpasync_wait0() {
    asm volatile("cp.async.wait_group 0;");
}

// =====================================================================
// kernel 0: pre-round weights to tf32 (RN); build concatenated Wq
// =====================================================================
__global__ void __launch_bounds__(256) k_roundW(
    const float* __restrict__ Wv,  const float* __restrict__ Wo,
    const float* __restrict__ Woff, const float* __restrict__ Wattn)
{
    int id = blockIdx.x * 256 + threadIdx.x;          // 0..65535
    g_Wvr[id] = wmma::__float_to_tf32(Wv[id]);
    g_Wor[id] = wmma::__float_to_tf32(Wo[id]);
    if (id < CD * 96) {
        int k = id / 96, c = id % 96;
        float v = (c < 64) ? Woff[k * 64 + c] : Wattn[k * 32 + (c - 64)];
        g_Wq[id] = wmma::__float_to_tf32(v);
    }
}

// =====================================================================
// kernel 1a: offsets/logits GEMM  P[8192,96] = query @ Wq   (64 CTAs, 1 wave)
// BM=128, BN=96; 8 warps as 4(row)x2(col): acc 2x3 frags of 16x16
// =====================================================================
#define OLDA 20
#define OLDB 100

struct __align__(16) SmemOff {
    float a[2][128 * OLDA];       // 20.5 KB
    float b[2][16 * OLDB];        // 12.8 KB
};

__global__ void __launch_bounds__(256)
k_offgemm(const float* __restrict__ query)
{
    __shared__ SmemOff sm;
    int tid = threadIdx.x;
    int wid = tid >> 5;
    int wr = wid & 3;             // 4 row groups of 32
    int wc = wid >> 2;            // 2 col groups of 48
    int m0 = blockIdx.x * 128;

    wmma::fragment<wmma::accumulator, 16, 16, 8, float> acc[2][3];
    #pragma unroll
    for (int i = 0; i < 2; i++)
        #pragma unroll
        for (int j = 0; j < 3; j++) wmma::fill_fragment(acc[i][j], 0.0f);

    auto load_tiles = [&](int buf, int k0) {
        // A: 128x16 = 512 f4, 2/thread
        #pragma unroll
        for (int i = 0; i < 2; i++) {
            int f4 = tid + i * 256;
            int r = f4 >> 2, c4 = f4 & 3;
            cpasync16(&sm.a[buf][r * OLDA + c4 * 4],
                      query + (size_t)(m0 + r) * CD + k0 + c4 * 4);
        }
        // B: 16x96 = 384 f4
        #pragma unroll
        for (int i = 0; i < 2; i++) {
            int f = tid + i * 256;
            if (f < 384) {
                int r = f / 24, c4 = f % 24;
                cpasync16(&sm.b[buf][r * OLDB + c4 * 4],
                          g_Wq + (size_t)(k0 + r) * 96 + c4 * 4);
            }
        }
        cpasync_commit();
    };

    load_tiles(0, 0);

    const int NIT = CD / 16;      // 16
    for (int it = 0; it < NIT; ++it) {
        cpasync_wait0();
        __syncthreads();
        if (it + 1 < NIT) load_tiles((it + 1) & 1, (it + 1) * 16);

        int buf = it & 1;
        #pragma unroll
        for (int kk = 0; kk < 16; kk += 8) {
            wmma::fragment<wmma::matrix_a, 16, 16, 8, wmma::precision::tf32, wmma::row_major> af[2];
            wmma::fragment<wmma::matrix_b, 16, 16, 8, wmma::precision::tf32, wmma::row_major> bf[3];
            #pragma unroll
            for (int i = 0; i < 2; i++) {
                wmma::load_matrix_sync(af[i], &sm.a[buf][(wr * 32 + i * 16) * OLDA + kk], OLDA);
                #pragma unroll
                for (int e = 0; e < af[i].num_elements; e++)
                    af[i].x[e] = wmma::__float_to_tf32(af[i].x[e]);   // query is raw fp32
            }
            #pragma unroll
            for (int j = 0; j < 3; j++)
                wmma::load_matrix_sync(bf[j], &sm.b[buf][kk * OLDB + wc * 48 + j * 16], OLDB);
            #pragma unroll
            for (int i = 0; i < 2; i++)
                #pragma unroll
                for (int j = 0; j < 3; j++)
                    wmma::mma_sync(acc[i][j], af[i], bf[j], acc[i][j]);
        }
        __syncthreads();
    }

    // epilogue: store fragments straight to g_P (row stride 96, mult of 4)
    #pragma unroll
    for (int i = 0; i < 2; i++)
        #pragma unroll
        for (int j = 0; j < 3; j++)
            wmma::store_matrix_sync(g_P + (size_t)(m0 + wr * 32 + i * 16) * 96 + wc * 48 + j * 16,
                                    acc[i][j], 96, wmma::mem_row_major);
}

// =====================================================================
// kernel 1b: finalize — softmax over points + pixel coords -> g_samp
// =====================================================================
__global__ void __launch_bounds__(256) k_finalize(
    const float* __restrict__ refp,
    const float* __restrict__ boff, const float* __restrict__ battn)
{
    int id = blockIdx.x * 256 + threadIdx.x;   // 0..262143 = bq*32 + t32
    int bq = id >> 5, t32 = id & 31;
    int h = t32 >> 2, p = t32 & 3;

    const float* prow = g_P + (size_t)bq * 96;
    float l0 = prow[64 + h * 4 + 0] + battn[h * 4 + 0];
    float l1 = prow[64 + h * 4 + 1] + battn[h * 4 + 1];
    float l2 = prow[64 + h * 4 + 2] + battn[h * 4 + 2];
    float l3 = prow[64 + h * 4 + 3] + battn[h * 4 + 3];
    float m  = fmaxf(fmaxf(l0, l1), fmaxf(l2, l3));
    float e0 = __expf(l0 - m), e1 = __expf(l1 - m);
    float e2 = __expf(l2 - m), e3 = __expf(l3 - m);
    float inv = 1.0f / (e0 + e1 + e2 + e3);
    float ep  = (p == 0) ? e0 : (p == 1) ? e1 : (p == 2) ? e2 : e3;
    float w   = ep * inv;

    float ox = prow[(h * NPT + p) * 2 + 0] + boff[(h * NPT + p) * 2 + 0];
    float oy = prow[(h * NPT + p) * 2 + 1] + boff[(h * NPT + p) * 2 + 1];
    float refx = refp[bq * 2 + 0];
    float refy = refp[bq * 2 + 1];
    // grid_sample align_corners=False: pix = (ref + off/Dim)*Dim - 0.5
    float x = refx * (float)WWp + ox - 0.5f;
    float y = refy * (float)HH  + oy - 0.5f;
    g_samp[(size_t)bq * (NH * NPT) + t32] = make_float4(x, y, w, 0.f);
}

// =====================================================================
// kernel 2: weighted gather of RAW memory rows (R11 structure, measured good:
// block = query -> all 8 heads share the L1-hot pixel neighborhood).
// Epilogue rounds to tf32 so gemmS skips in-register conversion.
// =====================================================================
__global__ void __launch_bounds__(256) k_gather(const float* __restrict__ memory)
{
    int bq   = blockIdx.x;
    int h    = threadIdx.x >> 5;
    int lane = threadIdx.x & 31;
    int b    = bq >> 10;

    const float* mb = memory + (size_t)b * HWSZ * CD + lane * 8;

    float acc[8] = {0.f, 0.f, 0.f, 0.f, 0.f, 0.f, 0.f, 0.f};
    float s = 0.f;

    #pragma unroll
    for (int p = 0; p < NPT; p++) {
        float4 sm = g_samp[(size_t)bq * (NH * NPT) + h * NPT + p];
        float x = sm.x, y = sm.y, w = sm.z;
        float xf = floorf(x), yf = floorf(y);
        int ix = (int)xf, iy = (int)yf;
        float fx = x - xf, fy = y - yf;
        float w00 = w * (1.0f - fy) * (1.0f - fx);
        float w01 = w * (1.0f - fy) * fx;
        float w10 = w * fy * (1.0f - fx);
        float w11 = w * fy * fx;

        if ((unsigned)ix < (WWp - 1) && (unsigned)iy < (HH - 1)) {
            const float* c00 = mb + (size_t)(iy * WWp + ix) * CD;
            float4 a0 = *(const float4*)(c00);
            float4 a1 = *(const float4*)(c00 + 4);
            float4 b0 = *(const float4*)(c00 + CD);
            float4 b1 = *(const float4*)(c00 + CD + 4);
            float4 c0 = *(const float4*)(c00 + WWp * CD);
            float4 c1 = *(const float4*)(c00 + WWp * CD + 4);
            float4 d0 = *(const float4*)(c00 + WWp * CD + CD);
            float4 d1 = *(const float4*)(c00 + WWp * CD + CD + 4);
            acc[0] += w00 * a0.x + w01 * b0.x + w10 * c0.x + w11 * d0.x;
            acc[1] += w00 * a0.y + w01 * b0.y + w10 * c0.y + w11 * d0.y;
            acc[2] += w00 * a0.z + w01 * b0.z + w10 * c0.z + w11 * d0.z;
            acc[3] += w00 * a0.w + w01 * b0.w + w10 * c0.w + w11 * d0.w;
            acc[4] += w00 * a1.x + w01 * b1.x + w10 * c1.x + w11 * d1.x;
            acc[5] += w00 * a1.y + w01 * b1.y + w10 * c1.y + w11 * d1.y;
            acc[6] += w00 * a1.z + w01 * b1.z + w10 * c1.z + w11 * d1.z;
            acc[7] += w00 * a1.w + w01 * b1.w + w10 * c1.w + w11 * d1.w;
            s += w;
        } else {
            #pragma unroll
            for (int cy = 0; cy < 2; cy++) {
                int yy = iy + cy;
                if ((unsigned)yy >= HH) continue;
                #pragma unroll
                for (int cx = 0; cx < 2; cx++) {
                    int xx = ix + cx;
                    if ((unsigned)xx >= WWp) continue;
                    float cw = cy ? (cx ? w11 : w10) : (cx ? w01 : w00);
                    const float* cp = mb + (size_t)(yy * WWp + xx) * CD;
                    float4 u0 = *(const float4*)(cp);
                    float4 u1 = *(const float4*)(cp + 4);
                    acc[0] += cw * u0.x; acc[1] += cw * u0.y;
                    acc[2] += cw * u0.z; acc[3] += cw * u0.w;
                    acc[4] += cw * u1.x; acc[5] += cw * u1.y;
                    acc[6] += cw * u1.z; acc[7] += cw * u1.w;
                    s += cw;
                }
            }
        }
    }

    #pragma unroll
    for (int i = 0; i < 8; i++) acc[i] = wmma::__float_to_tf32(acc[i]);

    float* urow = g_U + ((size_t)h * NQ + bq) * CD + lane * 8;
    *(float4*)(urow)     = make_float4(acc[0], acc[1], acc[2], acc[3]);
    *(float4*)(urow + 4) = make_float4(acc[4], acc[5], acc[6], acc[7]);
    if (lane == 0) g_sw[(size_t)bq * NH + h] = s;
}

// =====================================================================
// kernel 3: per-head value projection (inputs pre-rounded: no in-reg cvt)
// =====================================================================
#define SBM 128
#define SBK 16
#define SLDA 20
#define SLDB 36
#define SLDC 36

struct __align__(16) SmemS {
    union {
        struct { float a[2][SBM * SLDA]; float b[2][SBK * SLDB]; } ab;
        float c[SBM * SLDC];
    };
};

__global__ void __launch_bounds__(256)
k_gemmS(const float* __restrict__ bv)
{
    __shared__ SmemS sm;
    int h   = blockIdx.y;
    int m0  = blockIdx.x * SBM;
    int tid = threadIdx.x;
    int warpId = tid >> 5;

    const float* A = g_U + (size_t)h * NQ * CD;

    wmma::fragment<wmma::accumulator, 16, 16, 8, float> acc[2];
    wmma::fill_fragment(acc[0], 0.0f);
    wmma::fill_fragment(acc[1], 0.0f);

    auto load_tiles = [&](int buf, int k0) {
        #pragma unroll
        for (int i = 0; i < 2; i++) {
            int f4 = tid + i * 256;
            int r = f4 >> 2, c4 = f4 & 3;
            cpasync16(&sm.ab.a[buf][r * SLDA + c4 * 4],
                      A + (size_t)(m0 + r) * CD + k0 + c4 * 4);
        }
        if (tid < 128) {
            int r = tid >> 3, c4 = tid & 7;
            cpasync16(&sm.ab.b[buf][r * SLDB + c4 * 4],
                      g_Wvr + (size_t)(k0 + r) * CD + h * 32 + c4 * 4);
        }
        cpasync_commit();
    };

    load_tiles(0, 0);

    const int NIT = CD / SBK;
    for (int it = 0; it < NIT; ++it) {
        cpasync_wait0();
        __syncthreads();
        if (it + 1 < NIT) load_tiles((it + 1) & 1, (it + 1) * SBK);

        int buf = it & 1;
        #pragma unroll
        for (int kk = 0; kk < SBK; kk += 8) {
            wmma::fragment<wmma::matrix_a, 16, 16, 8, wmma::precision::tf32, wmma::row_major> af;
            wmma::fragment<wmma::matrix_b, 16, 16, 8, wmma::precision::tf32, wmma::row_major> bf[2];
            wmma::load_matrix_sync(af, &sm.ab.a[buf][(warpId * 16) * SLDA + kk], SLDA);
            #pragma unroll
            for (int j = 0; j < 2; j++) {
                wmma::load_matrix_sync(bf[j], &sm.ab.b[buf][kk * SLDB + j * 16], SLDB);
                wmma::mma_sync(acc[j], af, bf[j], acc[j]);
            }
        }
        __syncthreads();
    }

    #pragma unroll
    for (int j = 0; j < 2; j++)
        wmma::store_matrix_sync(&sm.c[(warpId * 16) * SLDC + j * 16], acc[j],
                                SLDC, wmma::mem_row_major);
    __syncthreads();

    // epilogue: + s*bv in fp32, then tf32-round for gemmO's A operand
    #pragma unroll
    for (int i = 0; i < 4; i++) {
        int f4 = i * 256 + tid;
        int r = f4 >> 3, c4 = f4 & 7;
        float s = g_sw[(size_t)(m0 + r) * NH + h];
        float4 v  = *(float4*)&sm.c[r * SLDC + c4 * 4];
        float4 bb = *(const float4*)(bv + h * 32 + c4 * 4);
        v.x = wmma::__float_to_tf32(v.x + s * bb.x);
        v.y = wmma::__float_to_tf32(v.y + s * bb.y);
        v.z = wmma::__float_to_tf32(v.z + s * bb.z);
        v.w = wmma::__float_to_tf32(v.w + s * bb.w);
        *(float4*)&g_S[(size_t)(m0 + r) * CD + h * 32 + c4 * 4] = v;
    }
}

// =====================================================================
// kernel 4: output projection GEMM (BM=128 x BN=64, 3 stages; no in-reg cvt)
// =====================================================================
#define BM 128
#define BN 64
#define BK 16
#define NSTG 3
#define LDA 20
#define LDB 68
#define LDC 68

struct __align__(16) SmemGemm {
    union {
        struct { float a[NSTG][BM * LDA]; float b[NSTG][BK * LDB]; } ab;
        float c[BM * LDC];
    };
};

__global__ void __launch_bounds__(256)
k_gemmO(const float* __restrict__ bias, float* __restrict__ out)
{
    __shared__ SmemGemm sm;
    const float* A = (const float*)g_S;

    int n0 = blockIdx.x * BN;
    int m0 = blockIdx.y * BM;
    int tid = threadIdx.x;
    int warpId = tid >> 5;
    int wr = warpId >> 1;
    int wc = warpId & 1;

    wmma::fragment<wmma::accumulator, 16, 16, 8, float> acc[2][2];
    #pragma unroll
    for (int i = 0; i < 2; i++)
        #pragma unroll
        for (int j = 0; j < 2; j++) wmma::fill_fragment(acc[i][j], 0.0f);

    auto load_tiles = [&](int buf, int k0) {
        #pragma unroll
        for (int i = 0; i < 2; i++) {
            int f4 = tid + i * 256;
            int r = f4 >> 2, c4 = f4 & 3;
            cpasync16(&sm.ab.a[buf][r * LDA + c4 * 4],
                      A + (size_t)(m0 + r) * CD + k0 + c4 * 4);
        }
        {
            int r = tid >> 4, c4 = tid & 15;
            cpasync16(&sm.ab.b[buf][r * LDB + c4 * 4],
                      g_Wor + (size_t)(k0 + r) * CD + n0 + c4 * 4);
        }
        cpasync_commit();
    };

    load_tiles(0, 0);
    load_tiles(1, BK);

    const int NIT = CD / BK;
    for (int it = 0; it < NIT; ++it) {
        asm volatile("cp.async.wait_group 1;");
        __syncthreads();
        if (it + 2 < NIT) load_tiles((it + 2) % NSTG, (it + 2) * BK);
        else              cpasync_commit();

        int buf = it % NSTG;
        #pragma unroll
        for (int kk = 0; kk < BK; kk += 8) {
            wmma::fragment<wmma::matrix_a, 16, 16, 8, wmma::precision::tf32, wmma::row_major> af[2];
            wmma::fragment<wmma::matrix_b, 16, 16, 8, wmma::precision::tf32, wmma::row_major> bf[2];
            #pragma unroll
            for (int i = 0; i < 2; i++)
                wmma::load_matrix_sync(af[i], &sm.ab.a[buf][(wr * 32 + i * 16) * LDA + kk], LDA);
            #pragma unroll
            for (int j = 0; j < 2; j++)
                wmma::load_matrix_sync(bf[j], &sm.ab.b[buf][kk * LDB + wc * 32 + j * 16], LDB);
            #pragma unroll
            for (int i = 0; i < 2; i++)
                #pragma unroll
                for (int j = 0; j < 2; j++)
                    wmma::mma_sync(acc[i][j], af[i], bf[j], acc[i][j]);
        }
        __syncthreads();
    }

    #pragma unroll
    for (int i = 0; i < 2; i++)
        #pragma unroll
        for (int j = 0; j < 2; j++)
            wmma::store_matrix_sync(&sm.c[(wr * 32 + i * 16) * LDC + wc * 32 + j * 16],
                                    acc[i][j], LDC, wmma::mem_row_major);
    __syncthreads();

    #pragma unroll
    for (int i = 0; i < 8; i++) {
        int id = i * 256 + tid;
        int r = id >> 4, c4 = id & 15;
        float4 v = *(float4*)&sm.c[r * LDC + c4 * 4];
        int col = n0 + c4 * 4;
        v.x += bias[col]; v.y += bias[col + 1]; v.z += bias[col + 2]; v.w += bias[col + 3];
        *(float4*)&out[(size_t)(m0 + r) * CD + col] = v;
    }
}

// ---------------- launch -----------------------------------------------------
extern "C" void kernel_launch(void* const* d_in, const int* in_sizes, int n_in,
                              void* d_out, int out_size)
{
    const float* query  = (const float*)d_in[0];
    const float* memory = (const float*)d_in[1];
    const float* refp   = (const float*)d_in[2];
    const float* Wv     = (const float*)d_in[3];
    const float* bv     = (const float*)d_in[4];
    const float* Woff   = (const float*)d_in[5];
    const float* boff   = (const float*)d_in[6];
    const float* Wattn  = (const float*)d_in[7];
    const float* battn  = (const float*)d_in[8];
    const float* Wout   = (const float*)d_in[9];
    const float* bout   = (const float*)d_in[10];
    float* out = (float*)d_out;

    // 0) pre-round weights to tf32
    k_roundW<<<CD * CD / 256, 256>>>(Wv, Wout, Woff, Wattn);

    // 1a) offsets/logits GEMM (64 CTAs, single wave)
    k_offgemm<<<NQ / 128, 256>>>(query);

    // 1b) softmax + pixel coords
    k_finalize<<<NQ * 32 / 256, 256>>>(refp, boff, battn);

    // 2) weighted gather of raw memory rows (block = query, heads share L1)
    k_gather<<<NQ, 256>>>(memory);

    // 3) per-head value projection (+ s*bv bias term)
    k_gemmS<<<dim3(NQ / SBM, NH), 256>>>(bv);

    // 4) output projection GEMM
    k_gemmO<<<dim3(CD / BN, NQ / BM), 256>>>(bout, out);
}

// round 16
// speedup vs baseline: 1.9134x; 1.1972x over previous
#include <cstdint>
#include <cuda_runtime.h>
#include <mma.h>

using namespace nvcuda;

// Problem constants (fixed shapes per reference setup_inputs)
#define NB   8
#define LQ   1024
#define CD   256
#define NH   8
#define NPT  4
#define HD   32
#define HH   128
#define WWp  128
#define HWSZ (HH * WWp)
#define NQ   (NB * LQ)      // 8192

// ---------------- scratch (device globals; no allocations allowed) ----------
__device__ float4 g_samp[(size_t)NQ * NH * NPT];      // (x_pix, y_pix, attn_w, _)
__device__ float  g_U[(size_t)NH * NQ * CD];          // gathered rows (tf32-rounded)
__device__ float  g_sw[(size_t)NQ * NH];              // sum of effective weights
__device__ float  g_S[(size_t)NQ * CD];               // sampled values (tf32-rounded)
__device__ float  g_P[(size_t)NQ * 96];               // offsets(64) | attn logits(32)
__device__ float  g_Wvr[CD * CD];                     // tf32-rounded Wv
__device__ float  g_Wor[CD * CD];                     // tf32-rounded Wout
__device__ float  g_Wq[CD * 96];                      // tf32-rounded [Woff | Wattn]

// ---------------- cp.async helpers ------------------------------------------
__device__ __forceinline__ void cpasync16(void* smem_dst, const void* gmem_src) {
    unsigned int s = (unsigned int)__cvta_generic_to_shared(smem_dst);
    asm volatile("cp.async.cg.shared.global [%0], [%1], 16;" :: "r"(s), "l"(gmem_src));
}
__device__ __forceinline__ void cpasync_commit() {
    asm volatile("cp.async.commit_group;");
}
__device__ __forceinline__ void cpasync_wait0() {
    asm volatile("cp.async.wait_group 0;");
}

// =====================================================================
// kernel 0: pre-round weights to tf32 (RN); build concatenated Wq
// =====================================================================
__global__ void __launch_bounds__(256) k_roundW(
    const float* __restrict__ Wv,  const float* __restrict__ Wo,
    const float* __restrict__ Woff, const float* __restrict__ Wattn)
{
    int id = blockIdx.x * 256 + threadIdx.x;          // 0..65535
    g_Wvr[id] = wmma::__float_to_tf32(Wv[id]);
    g_Wor[id] = wmma::__float_to_tf32(Wo[id]);
    if (id < CD * 96) {
        int k = id / 96, c = id % 96;
        float v = (c < 64) ? Woff[k * 64 + c] : Wattn[k * 32 + (c - 64)];
        g_Wq[id] = wmma::__float_to_tf32(v);
    }
}

// =====================================================================
// kernel 1a: offsets/logits GEMM  P[8192,96] = query @ Wq   (64 CTAs, 1 wave)
// =====================================================================
#define OLDA 20
#define OLDB 100

struct __align__(16) SmemOff {
    float a[2][128 * OLDA];       // 20.5 KB
    float b[2][16 * OLDB];        // 12.8 KB
};

__global__ void __launch_bounds__(256)
k_offgemm(const float* __restrict__ query)
{
    __shared__ SmemOff sm;
    int tid = threadIdx.x;
    int wid = tid >> 5;
    int wr = wid & 3;             // 4 row groups of 32
    int wc = wid >> 2;            // 2 col groups of 48
    int m0 = blockIdx.x * 128;

    wmma::fragment<wmma::accumulator, 16, 16, 8, float> acc[2][3];
    #pragma unroll
    for (int i = 0; i < 2; i++)
        #pragma unroll
        for (int j = 0; j < 3; j++) wmma::fill_fragment(acc[i][j], 0.0f);

    auto load_tiles = [&](int buf, int k0) {
        #pragma unroll
        for (int i = 0; i < 2; i++) {
            int f4 = tid + i * 256;
            int r = f4 >> 2, c4 = f4 & 3;
            cpasync16(&sm.a[buf][r * OLDA + c4 * 4],
                      query + (size_t)(m0 + r) * CD + k0 + c4 * 4);
        }
        #pragma unroll
        for (int i = 0; i < 2; i++) {
            int f = tid + i * 256;
            if (f < 384) {
                int r = f / 24, c4 = f % 24;
                cpasync16(&sm.b[buf][r * OLDB + c4 * 4],
                          g_Wq + (size_t)(k0 + r) * 96 + c4 * 4);
            }
        }
        cpasync_commit();
    };

    load_tiles(0, 0);

    const int NIT = CD / 16;      // 16
    for (int it = 0; it < NIT; ++it) {
        cpasync_wait0();
        __syncthreads();
        if (it + 1 < NIT) load_tiles((it + 1) & 1, (it + 1) * 16);

        int buf = it & 1;
        #pragma unroll
        for (int kk = 0; kk < 16; kk += 8) {
            wmma::fragment<wmma::matrix_a, 16, 16, 8, wmma::precision::tf32, wmma::row_major> af[2];
            wmma::fragment<wmma::matrix_b, 16, 16, 8, wmma::precision::tf32, wmma::row_major> bf[3];
            #pragma unroll
            for (int i = 0; i < 2; i++) {
                wmma::load_matrix_sync(af[i], &sm.a[buf][(wr * 32 + i * 16) * OLDA + kk], OLDA);
                #pragma unroll
                for (int e = 0; e < af[i].num_elements; e++)
                    af[i].x[e] = wmma::__float_to_tf32(af[i].x[e]);   // query is raw fp32
            }
            #pragma unroll
            for (int j = 0; j < 3; j++)
                wmma::load_matrix_sync(bf[j], &sm.b[buf][kk * OLDB + wc * 48 + j * 16], OLDB);
            #pragma unroll
            for (int i = 0; i < 2; i++)
                #pragma unroll
                for (int j = 0; j < 3; j++)
                    wmma::mma_sync(acc[i][j], af[i], bf[j], acc[i][j]);
        }
        __syncthreads();
    }

    #pragma unroll
    for (int i = 0; i < 2; i++)
        #pragma unroll
        for (int j = 0; j < 3; j++)
            wmma::store_matrix_sync(g_P + (size_t)(m0 + wr * 32 + i * 16) * 96 + wc * 48 + j * 16,
                                    acc[i][j], 96, wmma::mem_row_major);
}

// =====================================================================
// kernel 1b: finalize — softmax over points + pixel coords -> g_samp
// =====================================================================
__global__ void __launch_bounds__(256) k_finalize(
    const float* __restrict__ refp,
    const float* __restrict__ boff, const float* __restrict__ battn)
{
    int id = blockIdx.x * 256 + threadIdx.x;   // 0..262143 = bq*32 + t32
    int bq = id >> 5, t32 = id & 31;
    int h = t32 >> 2, p = t32 & 3;

    const float* prow = g_P + (size_t)bq * 96;
    float l0 = prow[64 + h * 4 + 0] + battn[h * 4 + 0];
    float l1 = prow[64 + h * 4 + 1] + battn[h * 4 + 1];
    float l2 = prow[64 + h * 4 + 2] + battn[h * 4 + 2];
    float l3 = prow[64 + h * 4 + 3] + battn[h * 4 + 3];
    float m  = fmaxf(fmaxf(l0, l1), fmaxf(l2, l3));
    float e0 = __expf(l0 - m), e1 = __expf(l1 - m);
    float e2 = __expf(l2 - m), e3 = __expf(l3 - m);
    float inv = 1.0f / (e0 + e1 + e2 + e3);
    float ep  = (p == 0) ? e0 : (p == 1) ? e1 : (p == 2) ? e2 : e3;
    float w   = ep * inv;

    float ox = prow[(h * NPT + p) * 2 + 0] + boff[(h * NPT + p) * 2 + 0];
    float oy = prow[(h * NPT + p) * 2 + 1] + boff[(h * NPT + p) * 2 + 1];
    float refx = refp[bq * 2 + 0];
    float refy = refp[bq * 2 + 1];
    // grid_sample align_corners=False: pix = (ref + off/Dim)*Dim - 0.5
    float x = refx * (float)WWp + ox - 0.5f;
    float y = refy * (float)HH  + oy - 0.5f;
    g_samp[(size_t)bq * (NH * NPT) + t32] = make_float4(x, y, w, 0.f);
}

// =====================================================================
// kernel 2: weighted gather of RAW memory rows.
// Block = query (8 heads share L1-hot neighborhood — measured good).
// DENSE lane mapping: lane l owns channels [4l,4l+4) and [128+4l,128+4l+4)
// -> each warp load is a contiguous 512B transaction (100% sector efficiency;
//    the old lane*8 mapping issued 32B-strided float4s = 50% efficiency).
// =====================================================================
__global__ void __launch_bounds__(256) k_gather(const float* __restrict__ memory)
{
    int bq   = blockIdx.x;
    int h    = threadIdx.x >> 5;
    int lane = threadIdx.x & 31;
    int b    = bq >> 10;

    // dense: first half at +lane*4, second half at +128+lane*4
    const float* mb = memory + (size_t)b * HWSZ * CD + lane * 4;

    float acc[8] = {0.f, 0.f, 0.f, 0.f, 0.f, 0.f, 0.f, 0.f};
    float s = 0.f;

    #pragma unroll
    for (int p = 0; p < NPT; p++) {
        float4 sm = g_samp[(size_t)bq * (NH * NPT) + h * NPT + p];
        float x = sm.x, y = sm.y, w = sm.z;
        float xf = floorf(x), yf = floorf(y);
        int ix = (int)xf, iy = (int)yf;
        float fx = x - xf, fy = y - yf;
        float w00 = w * (1.0f - fy) * (1.0f - fx);
        float w01 = w * (1.0f - fy) * fx;
        float w10 = w * fy * (1.0f - fx);
        float w11 = w * fy * fx;

        if ((unsigned)ix < (WWp - 1) && (unsigned)iy < (HH - 1)) {
            const float* c00 = mb + (size_t)(iy * WWp + ix) * CD;
            float4 a0 = *(const float4*)(c00);
            float4 a1 = *(const float4*)(c00 + 128);
            float4 b0 = *(const float4*)(c00 + CD);
            float4 b1 = *(const float4*)(c00 + CD + 128);
            float4 c0 = *(const float4*)(c00 + WWp * CD);
            float4 c1 = *(const float4*)(c00 + WWp * CD + 128);
            float4 d0 = *(const float4*)(c00 + WWp * CD + CD);
            float4 d1 = *(const float4*)(c00 + WWp * CD + CD + 128);
            acc[0] += w00 * a0.x + w01 * b0.x + w10 * c0.x + w11 * d0.x;
            acc[1] += w00 * a0.y + w01 * b0.y + w10 * c0.y + w11 * d0.y;
            acc[2] += w00 * a0.z + w01 * b0.z + w10 * c0.z + w11 * d0.z;
            acc[3] += w00 * a0.w + w01 * b0.w + w10 * c0.w + w11 * d0.w;
            acc[4] += w00 * a1.x + w01 * b1.x + w10 * c1.x + w11 * d1.x;
            acc[5] += w00 * a1.y + w01 * b1.y + w10 * c1.y + w11 * d1.y;
            acc[6] += w00 * a1.z + w01 * b1.z + w10 * c1.z + w11 * d1.z;
            acc[7] += w00 * a1.w + w01 * b1.w + w10 * c1.w + w11 * d1.w;
            s += w;
        } else {
            #pragma unroll
            for (int cy = 0; cy < 2; cy++) {
                int yy = iy + cy;
                if ((unsigned)yy >= HH) continue;
                #pragma unroll
                for (int cx = 0; cx < 2; cx++) {
                    int xx = ix + cx;
                    if ((unsigned)xx >= WWp) continue;
                    float cw = cy ? (cx ? w11 : w10) : (cx ? w01 : w00);
                    const float* cp = mb + (size_t)(yy * WWp + xx) * CD;
                    float4 u0 = *(const float4*)(cp);
                    float4 u1 = *(const float4*)(cp + 128);
                    acc[0] += cw * u0.x; acc[1] += cw * u0.y;
                    acc[2] += cw * u0.z; acc[3] += cw * u0.w;
                    acc[4] += cw * u1.x; acc[5] += cw * u1.y;
                    acc[6] += cw * u1.z; acc[7] += cw * u1.w;
                    s += cw;
                }
            }
        }
    }

    #pragma unroll
    for (int i = 0; i < 8; i++) acc[i] = wmma::__float_to_tf32(acc[i]);

    float* urow = g_U + ((size_t)h * NQ + bq) * CD;
    *(float4*)(urow + lane * 4)       = make_float4(acc[0], acc[1], acc[2], acc[3]);
    *(float4*)(urow + 128 + lane * 4) = make_float4(acc[4], acc[5], acc[6], acc[7]);
    if (lane == 0) g_sw[(size_t)bq * NH + h] = s;
}

// =====================================================================
// kernel 3: per-head value projection (inputs pre-rounded: no in-reg cvt)
// =====================================================================
#define SBM 128
#define SBK 16
#define SLDA 20
#define SLDB 36
#define SLDC 36

struct __align__(16) SmemS {
    union {
        struct { float a[2][SBM * SLDA]; float b[2][SBK * SLDB]; } ab;
        float c[SBM * SLDC];
    };
};

__global__ void __launch_bounds__(256)
k_gemmS(const float* __restrict__ bv)
{
    __shared__ SmemS sm;
    int h   = blockIdx.y;
    int m0  = blockIdx.x * SBM;
    int tid = threadIdx.x;
    int warpId = tid >> 5;

    const float* A = g_U + (size_t)h * NQ * CD;

    wmma::fragment<wmma::accumulator, 16, 16, 8, float> acc[2];
    wmma::fill_fragment(acc[0], 0.0f);
    wmma::fill_fragment(acc[1], 0.0f);

    auto load_tiles = [&](int buf, int k0) {
        #pragma unroll
        for (int i = 0; i < 2; i++) {
            int f4 = tid + i * 256;
            int r = f4 >> 2, c4 = f4 & 3;
            cpasync16(&sm.ab.a[buf][r * SLDA + c4 * 4],
                      A + (size_t)(m0 + r) * CD + k0 + c4 * 4);
        }
        if (tid < 128) {
            int r = tid >> 3, c4 = tid & 7;
            cpasync16(&sm.ab.b[buf][r * SLDB + c4 * 4],
                      g_Wvr + (size_t)(k0 + r) * CD + h * 32 + c4 * 4);
        }
        cpasync_commit();
    };

    load_tiles(0, 0);

    const int NIT = CD / SBK;
    for (int it = 0; it < NIT; ++it) {
        cpasync_wait0();
        __syncthreads();
        if (it + 1 < NIT) load_tiles((it + 1) & 1, (it + 1) * SBK);

        int buf = it & 1;
        #pragma unroll
        for (int kk = 0; kk < SBK; kk += 8) {
            wmma::fragment<wmma::matrix_a, 16, 16, 8, wmma::precision::tf32, wmma::row_major> af;
            wmma::fragment<wmma::matrix_b, 16, 16, 8, wmma::precision::tf32, wmma::row_major> bf[2];
            wmma::load_matrix_sync(af, &sm.ab.a[buf][(warpId * 16) * SLDA + kk], SLDA);
            #pragma unroll
            for (int j = 0; j < 2; j++) {
                wmma::load_matrix_sync(bf[j], &sm.ab.b[buf][kk * SLDB + j * 16], SLDB);
                wmma::mma_sync(acc[j], af, bf[j], acc[j]);
            }
        }
        __syncthreads();
    }

    #pragma unroll
    for (int j = 0; j < 2; j++)
        wmma::store_matrix_sync(&sm.c[(warpId * 16) * SLDC + j * 16], acc[j],
                                SLDC, wmma::mem_row_major);
    __syncthreads();

    // epilogue: + s*bv in fp32, then tf32-round for gemmO's A operand
    #pragma unroll
    for (int i = 0; i < 4; i++) {
        int f4 = i * 256 + tid;
        int r = f4 >> 3, c4 = f4 & 7;
        float s = g_sw[(size_t)(m0 + r) * NH + h];
        float4 v  = *(float4*)&sm.c[r * SLDC + c4 * 4];
        float4 bb = *(const float4*)(bv + h * 32 + c4 * 4);
        v.x = wmma::__float_to_tf32(v.x + s * bb.x);
        v.y = wmma::__float_to_tf32(v.y + s * bb.y);
        v.z = wmma::__float_to_tf32(v.z + s * bb.z);
        v.w = wmma::__float_to_tf32(v.w + s * bb.w);
        *(float4*)&g_S[(size_t)(m0 + r) * CD + h * 32 + c4 * 4] = v;
    }
}

// =====================================================================
// kernel 4: output projection GEMM (BM=128 x BN=64, 3 stages; no in-reg cvt)
// =====================================================================
#define BM 128
#define BN 64
#define BK 16
#define NSTG 3
#define LDA 20
#define LDB 68
#define LDC 68

struct __align__(16) SmemGemm {
    union {
        struct { float a[NSTG][BM * LDA]; float b[NSTG][BK * LDB]; } ab;
        float c[BM * LDC];
    };
};

__global__ void __launch_bounds__(256)
k_gemmO(const float* __restrict__ bias, float* __restrict__ out)
{
    __shared__ SmemGemm sm;
    const float* A = (const float*)g_S;

    int n0 = blockIdx.x * BN;
    int m0 = blockIdx.y * BM;
    int tid = threadIdx.x;
    int warpId = tid >> 5;
    int wr = warpId >> 1;
    int wc = warpId & 1;

    wmma::fragment<wmma::accumulator, 16, 16, 8, float> acc[2][2];
    #pragma unroll
    for (int i = 0; i < 2; i++)
        #pragma unroll
        for (int j = 0; j < 2; j++) wmma::fill_fragment(acc[i][j], 0.0f);

    auto load_tiles = [&](int buf, int k0) {
        #pragma unroll
        for (int i = 0; i < 2; i++) {
            int f4 = tid + i * 256;
            int r = f4 >> 2, c4 = f4 & 3;
            cpasync16(&sm.ab.a[buf][r * LDA + c4 * 4],
                      A + (size_t)(m0 + r) * CD + k0 + c4 * 4);
        }
        {
            int r = tid >> 4, c4 = tid & 15;
            cpasync16(&sm.ab.b[buf][r * LDB + c4 * 4],
                      g_Wor + (size_t)(k0 + r) * CD + n0 + c4 * 4);
        }
        cpasync_commit();
    };

    load_tiles(0, 0);
    load_tiles(1, BK);

    const int NIT = CD / BK;
    for (int it = 0; it < NIT; ++it) {
        asm volatile("cp.async.wait_group 1;");
        __syncthreads();
        if (it + 2 < NIT) load_tiles((it + 2) % NSTG, (it + 2) * BK);
        else              cpasync_commit();

        int buf = it % NSTG;
        #pragma unroll
        for (int kk = 0; kk < BK; kk += 8) {
            wmma::fragment<wmma::matrix_a, 16, 16, 8, wmma::precision::tf32, wmma::row_major> af[2];
            wmma::fragment<wmma::matrix_b, 16, 16, 8, wmma::precision::tf32, wmma::row_major> bf[2];
            #pragma unroll
            for (int i = 0; i < 2; i++)
                wmma::load_matrix_sync(af[i], &sm.ab.a[buf][(wr * 32 + i * 16) * LDA + kk], LDA);
            #pragma unroll
            for (int j = 0; j < 2; j++)
                wmma::load_matrix_sync(bf[j], &sm.ab.b[buf][kk * LDB + wc * 32 + j * 16], LDB);
            #pragma unroll
            for (int i = 0; i < 2; i++)
                #pragma unroll
                for (int j = 0; j < 2; j++)
                    wmma::mma_sync(acc[i][j], af[i], bf[j], acc[i][j]);
        }
        __syncthreads();
    }

    #pragma unroll
    for (int i = 0; i < 2; i++)
        #pragma unroll
        for (int j = 0; j < 2; j++)
            wmma::store_matrix_sync(&sm.c[(wr * 32 + i * 16) * LDC + wc * 32 + j * 16],
                                    acc[i][j], LDC, wmma::mem_row_major);
    __syncthreads();

    #pragma unroll
    for (int i = 0; i < 8; i++) {
        int id = i * 256 + tid;
        int r = id >> 4, c4 = id & 15;
        float4 v = *(float4*)&sm.c[r * LDC + c4 * 4];
        int col = n0 + c4 * 4;
        v.x += bias[col]; v.y += bias[col + 1]; v.z += bias[col + 2]; v.w += bias[col + 3];
        *(float4*)&out[(size_t)(m0 + r) * CD + col] = v;
    }
}

// ---------------- launch -----------------------------------------------------
extern "C" void kernel_launch(void* const* d_in, const int* in_sizes, int n_in,
                              void* d_out, int out_size)
{
    const float* query  = (const float*)d_in[0];
    const float* memory = (const float*)d_in[1];
    const float* refp   = (const float*)d_in[2];
    const float* Wv     = (const float*)d_in[3];
    const float* bv     = (const float*)d_in[4];
    const float* Woff   = (const float*)d_in[5];
    const float* boff   = (const float*)d_in[6];
    const float* Wattn  = (const float*)d_in[7];
    const float* battn  = (const float*)d_in[8];
    const float* Wout   = (const float*)d_in[9];
    const float* bout   = (const float*)d_in[10];
    float* out = (float*)d_out;

    // 0) pre-round weights to tf32
    k_roundW<<<CD * CD / 256, 256>>>(Wv, Wout, Woff, Wattn);

    // 1a) offsets/logits GEMM (64 CTAs, single wave)
    k_offgemm<<<NQ / 128, 256>>>(query);

    // 1b) softmax + pixel coords
    k_finalize<<<NQ * 32 / 256, 256>>>(refp, boff, battn);

    // 2) weighted gather of raw memory rows (dense lane mapping)
    k_gather<<<NQ, 256>>>(memory);

    // 3) per-head value projection (+ s*bv bias term)
    k_gemmS<<<dim3(NQ / SBM, NH), 256>>>(bv);

    // 4) output projection GEMM
    k_gemmO<<<dim3(CD / BN, NQ / BM), 256>>>(bout, out);
}